// round 14
// baseline (speedup 1.0000x reference)
#include <cuda_runtime.h>
#include <math.h>

#define NN 4096
#define MM 8192
#define GG 8
#define HH 128
#define NDD 16
#define EE 131072
#define WSP 132   // padded smem row stride (floats)
#define GRID 256  // mega-kernel grid; co-resident at 2 blocks/SM (148 SMs)

// ---------------- device scratch ----------------
__device__ float g_buf[2][NN*HH];   // 0: xw1, 1: xw2
__device__ int   g_cnt[NN];
__device__ int   g_rowptr[NN+1];    // doubles as fill cursor (consumed semantics)
__device__ int   g_csr[EE];
__device__ float g_dinv[NN];
__device__ float g_condsum[GG*HH];
__device__ float g_condcnt[GG];
__device__ float g_gh[GG*HH];
__device__ float g_sl[NN];
__device__ float g_sr[NN];
__device__ int   g_bar[768];        // 3 phases x 8 counters x 32-int stride

// ---------------- tf32 helpers ----------------
__device__ __forceinline__ void mma_tf32(float c[4],
        unsigned a0, unsigned a1, unsigned a2, unsigned a3,
        unsigned b0, unsigned b1) {
    asm volatile(
        "mma.sync.aligned.m16n8k8.row.col.f32.tf32.tf32.f32 "
        "{%0,%1,%2,%3}, {%4,%5,%6,%7}, {%8,%9}, {%0,%1,%2,%3};"
        : "+f"(c[0]), "+f"(c[1]), "+f"(c[2]), "+f"(c[3])
        : "r"(a0), "r"(a1), "r"(a2), "r"(a3), "r"(b0), "r"(b1));
}
__device__ __forceinline__ unsigned hi_of(float v) {
    return __float_as_uint(v) & 0xFFFFE000u;
}
__device__ __forceinline__ unsigned lo_of(float v, unsigned h) {
    return __float_as_uint(v - __uint_as_float(h));
}

// ---------------- software grid barrier (all GRID blocks co-resident) --------
__device__ __forceinline__ void grid_bar(int phase) {
    __syncthreads();
    if (threadIdx.x == 0) {
        __threadfence();                                  // release
        atomicAdd(&g_bar[(phase*8 + (blockIdx.x & 7))*32], 1);
        volatile int* vb = g_bar;
        int sum;
        do {
            __nanosleep(64);
            sum = 0;
            #pragma unroll
            for (int j = 0; j < 8; j++) sum += vb[(phase*8 + j)*32];
        } while (sum < GRID);
        __threadfence();                                  // acquire
    }
    __syncthreads();
}

// ================= K1: hist + cond_pool (self-detecting layout) ==============
__global__ void k_hist_cond(const int* __restrict__ dst,
                            const float* __restrict__ obj_x, const float* __restrict__ obj_pos,
                            const int* __restrict__ nuc, const void* central, const void* backbone,
                            const int* __restrict__ obatch,
                            const float* __restrict__ Wn, const float* __restrict__ bn) {
    const int t = threadIdx.x;
    if (blockIdx.x < 128) {
        const int e0 = (blockIdx.x*256 + t) * 4;
        int4 d0 = *(const int4*)(dst + e0);
        atomicAdd(&g_cnt[d0.x], 1); atomicAdd(&g_cnt[d0.y], 1);
        atomicAdd(&g_cnt[d0.z], 1); atomicAdd(&g_cnt[d0.w], 1);
        return;
    }
    __shared__ int bad0, bad1;
    __shared__ float sox[32*13];
    __shared__ float sop[32*3];
    __shared__ int   sob[32];
    __shared__ int   scond[32];
    if (t == 0) { bad0 = 0; bad1 = 0; }
    __syncthreads();
    if (t < 128 && (t & 3) != 0) {
        if (((const unsigned char*)central)[t])  atomicOr(&bad0, 1);
        if (((const unsigned char*)backbone)[t]) atomicOr(&bad1, 1);
    }
    const int m0 = (blockIdx.x - 128) * 32;
    for (int j = t; j < 32*13; j += 256) sox[j] = obj_x[m0*13 + j];
    for (int j = t; j < 32*3;  j += 256) sop[j] = obj_pos[m0*3 + j];
    __syncthreads();
    const int fC = !bad0, fB = !bad1;   // 1 => int32 layout
    if (t < 32) {
        int m = m0 + t;
        int nv = nuc[m];
        bool cen = fC ? (((const int*)central)[m] != 0) : (((const unsigned char*)central)[m] != 0);
        bool bb  = fB ? (((const int*)backbone)[m] != 0) : (((const unsigned char*)backbone)[m] != 0);
        bool base = !bb;
        scond[t] = (nv == 0) || (cen && base) || ((nv == 2) && base);
        sob[t] = obatch[m];
    }
    __syncthreads();
    if (t >= 128) return;
    const int c = t;
    float wnk[NDD];
    #pragma unroll
    for (int k = 0; k < NDD; k++) wnk[k] = Wn[k*HH + c];
    const float bnc = bn[c];
    float acc = 0.f, cntloc = 0.f; int cur_g = -1;
    for (int mm = 0; mm < 32; mm++) {
        if (!scond[mm]) continue;
        int g = sob[mm];
        float e = bnc;
        #pragma unroll
        for (int k = 0; k < 13; k++) e += sox[mm*13 + k] * wnk[k];
        #pragma unroll
        for (int k = 0; k < 3; k++)  e += sop[mm*3 + k] * wnk[13 + k];
        if (g != cur_g) {
            if (cur_g >= 0) {
                atomicAdd(&g_condsum[cur_g*HH + c], acc);
                if (c == 0) atomicAdd(&g_condcnt[cur_g], cntloc);
            }
            cur_g = g; acc = e; cntloc = 1.f;
        } else { acc += e; cntloc += 1.f; }
    }
    if (cur_g >= 0) {
        atomicAdd(&g_condsum[cur_g*HH + c], acc);
        if (c == 0) atomicAdd(&g_condcnt[cur_g], cntloc);
    }
}

// ========= K2: scan (block 0, cleans g_cnt + g_bar) + graph_h (1..8) =========
__global__ void k_scan_graph(const int* __restrict__ timestep,
                             const float* __restrict__ Wt, const float* __restrict__ bt,
                             const float* __restrict__ Wc, const float* __restrict__ bc) {
    if (blockIdx.x == 0) {
        __shared__ int s[1024];
        const int t = threadIdx.x;
        if (t < 768) g_bar[t] = 0;          // reset mega-kernel barriers
        int v0 = g_cnt[4*t], v1 = g_cnt[4*t+1], v2 = g_cnt[4*t+2], v3 = g_cnt[4*t+3];
        g_cnt[4*t] = 0; g_cnt[4*t+1] = 0; g_cnt[4*t+2] = 0; g_cnt[4*t+3] = 0;
        g_dinv[4*t]   = rsqrtf((float)(v0 + 1));
        g_dinv[4*t+1] = rsqrtf((float)(v1 + 1));
        g_dinv[4*t+2] = rsqrtf((float)(v2 + 1));
        g_dinv[4*t+3] = rsqrtf((float)(v3 + 1));
        int sum = v0 + v1 + v2 + v3;
        s[t] = sum; __syncthreads();
        for (int off = 1; off < 1024; off <<= 1) {
            int x = (t >= off) ? s[t - off] : 0;
            __syncthreads();
            s[t] += x;
            __syncthreads();
        }
        int excl = s[t] - sum;
        g_rowptr[4*t]   = excl;
        g_rowptr[4*t+1] = excl + v0;
        g_rowptr[4*t+2] = excl + v0 + v1;
        g_rowptr[4*t+3] = excl + v0 + v1 + v2;
        if (t == 1023) g_rowptr[NN] = excl + sum;
        return;
    }
    __shared__ float te[HH], pe[HH];
    const int g = blockIdx.x - 1, c = threadIdx.x;
    if (c < HH) {
        float tv = (float)timestep[g];
        const float L = 9.210340371976184f;
        if (c < 64) te[c] = cosf(tv * expf(-L * (float)c / 64.f));
        else        te[c] = sinf(tv * expf(-L * (float)(c - 64) / 64.f));
        float cntv = g_condcnt[g];
        pe[c] = g_condsum[g*HH + c] / fmaxf(cntv, 1.0f);
        g_condsum[g*HH + c] = 0.f;
    }
    __syncthreads();
    if (c == 0) g_condcnt[g] = 0.f;
    if (c < HH) {
        float a = bt[c] + bc[c];
        #pragma unroll 8
        for (int k = 0; k < HH; k++)
            a += te[k] * Wt[k*HH + c] + pe[k] * Wc[k*HH + c];
        g_gh[g*HH + c] = a;
    }
}

// ================= K3: MEGA — fill+gemm1 | agg1+gemm2 | agg2+head | edges ====
#define SMEM_MEGA ((HH*WSP + 32*WSP + 32*NDD + HH + 32) * 4)
__global__ void __launch_bounds__(512, 2)
k_mega(const int* __restrict__ esrc, const int* __restrict__ edst,
       const float* __restrict__ W1,
       const float* __restrict__ x, const int* __restrict__ bmap,
       const float* __restrict__ Wn, const float* __restrict__ bn,
       const float* __restrict__ b1, const float* __restrict__ W2,
       const float* __restrict__ b2,
       const float* __restrict__ Wo, const float* __restrict__ bo,
       const float* __restrict__ we, const float* __restrict__ bedge,
       float* __restrict__ out_nodes, float* __restrict__ out_edges) {
    extern __shared__ float sm[];
    const int t = threadIdx.x;
    const int lane = t & 31, w = t >> 5;      // warp 0..15
    const int b = blockIdx.x;

    // ============ P0: blocks [0,128) gemm1 ; [128,256) CSR fill ============
    if (b >= 128) {
        const int e0 = (b - 128)*1024 + t*2;
        int2 s0 = *(const int2*)(esrc + e0);
        int2 d0 = *(const int2*)(edst + e0);
        g_csr[atomicAdd(&g_rowptr[d0.x], 1)] = s0.x;
        g_csr[atomicAdd(&g_rowptr[d0.y], 1)] = s0.y;
    } else {
        float* Ws  = sm;                        // 128 x 132
        float* As  = sm + HH*WSP;               // 32 x 132
        float* xr  = As + 32*WSP;               // 32 x 16
        float* bns = xr + 32*NDD;               // 128
        int*   gidx = (int*)(bns + HH);         // 32
        const int i0 = b * 32;

        #pragma unroll
        for (int kt = 0; kt < 8; kt++) {
            int k = kt*16 + w;
            float4 v = ((const float4*)(W1 + k*HH))[lane];
            *(float4*)(Ws + k*WSP + lane*4) = v;
        }
        if (t < 128) bns[t] = bn[t];
        if (t < 32) gidx[t] = bmap[i0 + t];
        xr[t] = x[i0*NDD + t];
        __syncthreads();

        {
            const int c = t & 127, rg = t >> 7;
            float wnk[NDD];
            #pragma unroll
            for (int k = 0; k < NDD; k++) wnk[k] = Wn[k*HH + c];
            #pragma unroll
            for (int r8 = 0; r8 < 8; r8++) {
                int r = rg*8 + r8;
                float a = bns[c] + g_gh[gidx[r]*HH + c];
                #pragma unroll
                for (int k = 0; k < NDD; k++) a += xr[r*NDD + k] * wnk[k];
                As[r*WSP + c] = a;
            }
        }
        __syncthreads();

        const int g = lane >> 2, tig = lane & 3;
        const int rgb = w >> 3, wn = w & 7;
        const int n0 = wn * 16;
        float c0[4] = {0,0,0,0}, c1[4] = {0,0,0,0};
        const float* A0 = As + (rgb*16 + g)*WSP;
        const float* A1 = As + (rgb*16 + 8 + g)*WSP;
        #pragma unroll
        for (int kt = 0; kt < 16; kt++) {
            int k0 = kt*8;
            float av0 = A0[k0+tig],   av1 = A1[k0+tig];
            float av2 = A0[k0+tig+4], av3 = A1[k0+tig+4];
            unsigned ah0 = hi_of(av0), ah1 = hi_of(av1), ah2 = hi_of(av2), ah3 = hi_of(av3);
            unsigned al0 = lo_of(av0,ah0), al1 = lo_of(av1,ah1);
            unsigned al2 = lo_of(av2,ah2), al3 = lo_of(av3,ah3);
            const float* B0 = Ws + (k0+tig)*WSP;
            const float* B1 = Ws + (k0+tig+4)*WSP;
            float bv0 = B0[n0+g], bv1 = B1[n0+g], bv2 = B0[n0+8+g], bv3 = B1[n0+8+g];
            unsigned bh0 = hi_of(bv0), bh1 = hi_of(bv1), bh2 = hi_of(bv2), bh3 = hi_of(bv3);
            unsigned bl0 = lo_of(bv0,bh0), bl1 = lo_of(bv1,bh1);
            unsigned bl2 = lo_of(bv2,bh2), bl3 = lo_of(bv3,bh3);
            mma_tf32(c0, ah0,ah1,ah2,ah3, bh0,bh1);
            mma_tf32(c0, ah0,ah1,ah2,ah3, bl0,bl1);
            mma_tf32(c0, al0,al1,al2,al3, bh0,bh1);
            mma_tf32(c1, ah0,ah1,ah2,ah3, bh2,bh3);
            mma_tf32(c1, ah0,ah1,ah2,ah3, bl2,bl3);
            mma_tf32(c1, al0,al1,al2,al3, bh2,bh3);
        }
        const int r0 = i0 + rgb*16 + g, r1 = r0 + 8;
        const float d0 = g_dinv[r0], d1 = g_dinv[r1];
        *(float2*)&g_buf[0][r0*HH + n0 + 2*tig]     = make_float2(d0*c0[0], d0*c0[1]);
        *(float2*)&g_buf[0][r0*HH + n0 + 8 + 2*tig] = make_float2(d0*c1[0], d0*c1[1]);
        *(float2*)&g_buf[0][r1*HH + n0 + 2*tig]     = make_float2(d1*c0[2], d1*c0[3]);
        *(float2*)&g_buf[0][r1*HH + n0 + 8 + 2*tig] = make_float2(d1*c1[2], d1*c1[3]);
    }
    grid_bar(0);

    // ============ P1: agg1 + gemm2 (16 nodes/block) ============
    {
        float* Ws = sm;                 // 128 x 132
        float* As = sm + HH*WSP;        // 16 x 132
        #pragma unroll
        for (int kt = 0; kt < 8; kt++) {
            int k = kt*16 + w;
            float4 v = ((const float4*)(W2 + k*HH))[lane];
            *(float4*)(Ws + k*WSP + lane*4) = v;
        }

        const int i = b*16 + w;
        const float4* __restrict__ xw = (const float4*)g_buf[0];
        float4 acc = xw[i*32 + lane];
        const int s0 = (i == 0) ? 0 : g_rowptr[i-1];
        const int s1 = g_rowptr[i];
        int e = s0;
        for (; e + 8 <= s1; e += 8) {
            int a0 = g_csr[e],   a1 = g_csr[e+1], a2 = g_csr[e+2], a3 = g_csr[e+3];
            int a4 = g_csr[e+4], a5 = g_csr[e+5], a6 = g_csr[e+6], a7 = g_csr[e+7];
            float4 v0 = xw[a0*32 + lane], v1 = xw[a1*32 + lane];
            float4 v2 = xw[a2*32 + lane], v3 = xw[a3*32 + lane];
            float4 v4 = xw[a4*32 + lane], v5 = xw[a5*32 + lane];
            float4 v6 = xw[a6*32 + lane], v7 = xw[a7*32 + lane];
            acc.x += ((v0.x+v1.x)+(v2.x+v3.x)) + ((v4.x+v5.x)+(v6.x+v7.x));
            acc.y += ((v0.y+v1.y)+(v2.y+v3.y)) + ((v4.y+v5.y)+(v6.y+v7.y));
            acc.z += ((v0.z+v1.z)+(v2.z+v3.z)) + ((v4.z+v5.z)+(v6.z+v7.z));
            acc.w += ((v0.w+v1.w)+(v2.w+v3.w)) + ((v4.w+v5.w)+(v6.w+v7.w));
        }
        for (; e + 4 <= s1; e += 4) {
            int a0 = g_csr[e], a1 = g_csr[e+1], a2 = g_csr[e+2], a3 = g_csr[e+3];
            float4 v0 = xw[a0*32 + lane], v1 = xw[a1*32 + lane];
            float4 v2 = xw[a2*32 + lane], v3 = xw[a3*32 + lane];
            acc.x += (v0.x+v1.x)+(v2.x+v3.x);
            acc.y += (v0.y+v1.y)+(v2.y+v3.y);
            acc.z += (v0.z+v1.z)+(v2.z+v3.z);
            acc.w += (v0.w+v1.w)+(v2.w+v3.w);
        }
        for (; e < s1; e++) {
            float4 v = xw[g_csr[e]*32 + lane];
            acc.x += v.x; acc.y += v.y; acc.z += v.z; acc.w += v.w;
        }
        {
            const float di = g_dinv[i];
            const float4 b4 = ((const float4*)b1)[lane];
            float4 h;
            h.x = fmaxf(di*acc.x + b4.x, 0.f);
            h.y = fmaxf(di*acc.y + b4.y, 0.f);
            h.z = fmaxf(di*acc.z + b4.z, 0.f);
            h.w = fmaxf(di*acc.w + b4.w, 0.f);
            ((float4*)(As + w*WSP))[lane] = h;
        }
        __syncthreads();

        const int g = lane >> 2, tig = lane & 3;
        const int n0 = w * 8;
        float c0[4] = {0,0,0,0};
        const float* A0 = As + g*WSP;
        const float* A1 = As + (8 + g)*WSP;
        #pragma unroll
        for (int kt = 0; kt < 16; kt++) {
            int k0 = kt*8;
            float av0 = A0[k0+tig],   av1 = A1[k0+tig];
            float av2 = A0[k0+tig+4], av3 = A1[k0+tig+4];
            unsigned ah0 = hi_of(av0), ah1 = hi_of(av1), ah2 = hi_of(av2), ah3 = hi_of(av3);
            unsigned al0 = lo_of(av0,ah0), al1 = lo_of(av1,ah1);
            unsigned al2 = lo_of(av2,ah2), al3 = lo_of(av3,ah3);
            const float* B0 = Ws + (k0+tig)*WSP;
            const float* B1 = Ws + (k0+tig+4)*WSP;
            float bv0 = B0[n0+g], bv1 = B1[n0+g];
            unsigned bh0 = hi_of(bv0), bh1 = hi_of(bv1);
            unsigned bl0 = lo_of(bv0,bh0), bl1 = lo_of(bv1,bh1);
            mma_tf32(c0, ah0,ah1,ah2,ah3, bh0,bh1);
            mma_tf32(c0, ah0,ah1,ah2,ah3, bl0,bl1);
            mma_tf32(c0, al0,al1,al2,al3, bh0,bh1);
        }
        const int i0 = b*16;
        const int r0 = i0 + g, r1 = r0 + 8;
        const float d0 = g_dinv[r0], d1 = g_dinv[r1];
        *(float2*)&g_buf[1][r0*HH + n0 + 2*tig] = make_float2(d0*c0[0], d0*c0[1]);
        *(float2*)&g_buf[1][r1*HH + n0 + 2*tig] = make_float2(d1*c0[2], d1*c0[3]);
    }
    grid_bar(1);

    // ============ P2: agg2 + head (warp-per-node, 16 nodes/block) ============
    {
        const int i = b*16 + w;
        const float4* __restrict__ xw = (const float4*)g_buf[1];
        float4 acc = xw[i*32 + lane];
        const int s0 = (i == 0) ? 0 : g_rowptr[i-1];
        const int s1 = g_rowptr[i];
        int e = s0;
        for (; e + 8 <= s1; e += 8) {
            int a0 = g_csr[e],   a1 = g_csr[e+1], a2 = g_csr[e+2], a3 = g_csr[e+3];
            int a4 = g_csr[e+4], a5 = g_csr[e+5], a6 = g_csr[e+6], a7 = g_csr[e+7];
            float4 v0 = xw[a0*32 + lane], v1 = xw[a1*32 + lane];
            float4 v2 = xw[a2*32 + lane], v3 = xw[a3*32 + lane];
            float4 v4 = xw[a4*32 + lane], v5 = xw[a5*32 + lane];
            float4 v6 = xw[a6*32 + lane], v7 = xw[a7*32 + lane];
            acc.x += ((v0.x+v1.x)+(v2.x+v3.x)) + ((v4.x+v5.x)+(v6.x+v7.x));
            acc.y += ((v0.y+v1.y)+(v2.y+v3.y)) + ((v4.y+v5.y)+(v6.y+v7.y));
            acc.z += ((v0.z+v1.z)+(v2.z+v3.z)) + ((v4.z+v5.z)+(v6.z+v7.z));
            acc.w += ((v0.w+v1.w)+(v2.w+v3.w)) + ((v4.w+v5.w)+(v6.w+v7.w));
        }
        for (; e + 4 <= s1; e += 4) {
            int a0 = g_csr[e], a1 = g_csr[e+1], a2 = g_csr[e+2], a3 = g_csr[e+3];
            float4 v0 = xw[a0*32 + lane], v1 = xw[a1*32 + lane];
            float4 v2 = xw[a2*32 + lane], v3 = xw[a3*32 + lane];
            acc.x += (v0.x+v1.x)+(v2.x+v3.x);
            acc.y += (v0.y+v1.y)+(v2.y+v3.y);
            acc.z += (v0.z+v1.z)+(v2.z+v3.z);
            acc.w += (v0.w+v1.w)+(v2.w+v3.w);
        }
        for (; e < s1; e++) {
            float4 v = xw[g_csr[e]*32 + lane];
            acc.x += v.x; acc.y += v.y; acc.z += v.z; acc.w += v.w;
        }
        const float di = g_dinv[i];
        const float4 b4 = ((const float4*)b2)[lane];
        float4 h;
        h.x = fmaxf(di*acc.x + b4.x, 0.f);
        h.y = fmaxf(di*acc.y + b4.y, 0.f);
        h.z = fmaxf(di*acc.z + b4.z, 0.f);
        h.w = fmaxf(di*acc.w + b4.w, 0.f);

        const float4 wl4 = ((const float4*)we)[lane];
        const float4 wr4 = ((const float4*)we)[32 + lane];
        float pl = h.x*wl4.x + h.y*wl4.y + h.z*wl4.z + h.w*wl4.w;
        float pr = h.x*wr4.x + h.y*wr4.y + h.z*wr4.z + h.w*wr4.w;

        float p[NDD];
        #pragma unroll
        for (int c = 0; c < NDD; c++) p[c] = 0.f;
        const float4* Wo4 = (const float4*)Wo;
        float hv[4] = {h.x, h.y, h.z, h.w};
        #pragma unroll
        for (int j = 0; j < 4; j++) {
            int k = lane*4 + j;
            #pragma unroll
            for (int c4 = 0; c4 < 4; c4++) {
                float4 wv = Wo4[k*4 + c4];
                p[c4*4+0] += hv[j]*wv.x; p[c4*4+1] += hv[j]*wv.y;
                p[c4*4+2] += hv[j]*wv.z; p[c4*4+3] += hv[j]*wv.w;
            }
        }
        #pragma unroll
        for (int off = 16; off > 0; off >>= 1) {
            pl += __shfl_down_sync(0xffffffffu, pl, off);
            pr += __shfl_down_sync(0xffffffffu, pr, off);
            #pragma unroll
            for (int c = 0; c < NDD; c++)
                p[c] += __shfl_down_sync(0xffffffffu, p[c], off);
        }
        if (lane == 0) {
            g_sl[i] = pl;
            g_sr[i] = pr;
            float4* on4 = (float4*)(out_nodes + i*NDD);
            const float4* bo4 = (const float4*)bo;
            #pragma unroll
            for (int c4 = 0; c4 < 4; c4++) {
                float4 bb = bo4[c4];
                float4 v;
                v.x = p[c4*4+0] + bb.x; v.y = p[c4*4+1] + bb.y;
                v.z = p[c4*4+2] + bb.z; v.w = p[c4*4+3] + bb.w;
                on4[c4] = v;
            }
        }
    }
    grid_bar(2);

    // ============ P3: edges (row-pair balanced, 8 pairs/block) ============
    {
        const float be = bedge[0];
        for (int pidx = b; pidx < NN/2; pidx += GRID) {
            #pragma unroll
            for (int half = 0; half < 2; half++) {
                const int i = (half == 0) ? pidx : (NN - 2 - pidx);
                if (half == 1 && i <= pidx) break;
                const int cnt = NN - 1 - i;
                const long long off = (long long)i * (2LL*NN - i - 1) / 2;
                const float sl = g_sl[i] + be;
                float* o = out_edges + off;
                const float* sr = g_sr + i + 1;
                const int pre0 = (int)((4 - (off & 3)) & 3);
                const int pre = pre0 < cnt ? pre0 : cnt;
                if (t < pre) o[t] = sl + sr[t];
                const int nv = (cnt - pre) >> 2;
                float4* o4 = (float4*)(o + pre);
                for (int v = t; v < nv; v += 512) {
                    int j = pre + v*4;
                    float4 r;
                    r.x = sl + sr[j];   r.y = sl + sr[j+1];
                    r.z = sl + sr[j+2]; r.w = sl + sr[j+3];
                    o4[v] = r;
                }
                const int tail0 = pre + nv*4;
                const int rem = cnt - tail0;
                if (t < rem) o[tail0 + t] = sl + sr[tail0 + t];
            }
        }
    }
}

// ================= launch =================
extern "C" void kernel_launch(void* const* d_in, const int* in_sizes, int n_in,
                              void* d_out, int out_size) {
    const float* x        = (const float*)d_in[0];
    const int*   eidx     = (const int*)d_in[1];
    const int*   timestep = (const int*)d_in[2];
    const int*   bmap     = (const int*)d_in[3];
    const int*   nuc      = (const int*)d_in[4];
    const void*  central  = d_in[5];
    const void*  backbone = d_in[6];
    const float* obj_x    = (const float*)d_in[7];
    const float* obj_pos  = (const float*)d_in[8];
    const int*   obatch   = (const int*)d_in[9];
    const float* Wn = (const float*)d_in[10]; const float* bn = (const float*)d_in[11];
    const float* Wc = (const float*)d_in[12]; const float* bc = (const float*)d_in[13];
    const float* Wt = (const float*)d_in[14]; const float* bt = (const float*)d_in[15];
    const float* W1 = (const float*)d_in[16]; const float* b1 = (const float*)d_in[17];
    const float* W2 = (const float*)d_in[18]; const float* b2 = (const float*)d_in[19];
    const float* Wo = (const float*)d_in[20]; const float* bo = (const float*)d_in[21];
    const float* we = (const float*)d_in[22]; const float* be = (const float*)d_in[23];

    float* out = (float*)d_out;
    float* out_nodes = out;
    float* out_edges = out + NN*NDD;

    const int* esrc = eidx;
    const int* edst = eidx + EE;

    cudaFuncSetAttribute(k_mega, cudaFuncAttributeMaxDynamicSharedMemorySize, SMEM_MEGA);

    k_hist_cond<<<384, 256>>>(edst, obj_x, obj_pos, nuc, central, backbone, obatch, Wn, bn);
    k_scan_graph<<<9, 1024>>>(timestep, Wt, bt, Wc, bc);
    k_mega<<<GRID, 512, SMEM_MEGA>>>(esrc, edst, W1, x, bmap, Wn, bn,
                                     b1, W2, b2, Wo, bo, we, be,
                                     out_nodes, out_edges);
}

// round 15
// speedup vs baseline: 1.0720x; 1.0720x over previous
#include <cuda_runtime.h>
#include <math.h>

#define NN 4096
#define MM 8192
#define GG 8
#define HH 128
#define NDD 16
#define EE 131072
#define WSP 132   // padded smem row stride (floats)
#define CAP 128   // slot-CSR capacity per node (Poisson(32) max ~62)

// ---------------- device scratch ----------------
__device__ float g_buf[2][NN*HH];   // 0: xw1, 1: xw2
__device__ int   g_cnt[NN];         // degree; zeroed by k_agg_head (self-clean)
__device__ int   g_csr2[NN*CAP];    // slot CSR
__device__ float g_dinv[NN];
__device__ float g_condsum[GG*HH];
__device__ float g_condcnt[GG];
__device__ float g_gh[GG*HH];
__device__ float g_sl[NN];
__device__ float g_sr[NN];

// ---------------- tf32 helpers ----------------
// mma.tf32 truncates the low 13 mantissa bits of each fp32 operand register,
// so raw v acts as hi; lo = v - trunc(v) is exact (Sterbenz).
__device__ __forceinline__ void mma_tf32(float c[4],
        unsigned a0, unsigned a1, unsigned a2, unsigned a3,
        unsigned b0, unsigned b1) {
    asm volatile(
        "mma.sync.aligned.m16n8k8.row.col.f32.tf32.tf32.f32 "
        "{%0,%1,%2,%3}, {%4,%5,%6,%7}, {%8,%9}, {%0,%1,%2,%3};"
        : "+f"(c[0]), "+f"(c[1]), "+f"(c[2]), "+f"(c[3])
        : "r"(a0), "r"(a1), "r"(a2), "r"(a3), "r"(b0), "r"(b1));
}
__device__ __forceinline__ unsigned hi_of(float v) {
    return __float_as_uint(v) & 0xFFFFE000u;
}
__device__ __forceinline__ unsigned lo_of(float v, unsigned h) {
    return __float_as_uint(v - __uint_as_float(h));
}

// ======== K1: hist+fill fused (blocks 0..127) + cond pool (128..383) =========
__global__ void k_hist_cond(const int* __restrict__ src, const int* __restrict__ dst,
                            const float* __restrict__ obj_x, const float* __restrict__ obj_pos,
                            const int* __restrict__ nuc, const void* central, const void* backbone,
                            const int* __restrict__ obatch,
                            const float* __restrict__ Wn, const float* __restrict__ bn) {
    const int t = threadIdx.x;
    if (blockIdx.x < 128) {
        const int e0 = (blockIdx.x*256 + t) * 4;
        int4 s0 = *(const int4*)(src + e0);
        int4 d0 = *(const int4*)(dst + e0);
        int p0 = atomicAdd(&g_cnt[d0.x], 1);
        int p1 = atomicAdd(&g_cnt[d0.y], 1);
        int p2 = atomicAdd(&g_cnt[d0.z], 1);
        int p3 = atomicAdd(&g_cnt[d0.w], 1);
        g_csr2[(d0.x << 7) + p0] = s0.x;
        g_csr2[(d0.y << 7) + p1] = s0.y;
        g_csr2[(d0.z << 7) + p2] = s0.z;
        g_csr2[(d0.w << 7) + p3] = s0.w;
        return;
    }
    // cond pooling: layout self-detect from first 128 bytes
    __shared__ int bad0, bad1;
    __shared__ float sox[32*13];
    __shared__ float sop[32*3];
    __shared__ int   sob[32];
    __shared__ int   scond[32];
    if (t == 0) { bad0 = 0; bad1 = 0; }
    __syncthreads();
    if (t < 128 && (t & 3) != 0) {
        if (((const unsigned char*)central)[t])  atomicOr(&bad0, 1);
        if (((const unsigned char*)backbone)[t]) atomicOr(&bad1, 1);
    }
    const int m0 = (blockIdx.x - 128) * 32;
    for (int j = t; j < 32*13; j += 256) sox[j] = obj_x[m0*13 + j];
    for (int j = t; j < 32*3;  j += 256) sop[j] = obj_pos[m0*3 + j];
    __syncthreads();
    const int fC = !bad0, fB = !bad1;   // 1 => int32 layout
    if (t < 32) {
        int m = m0 + t;
        int nv = nuc[m];
        bool cen = fC ? (((const int*)central)[m] != 0) : (((const unsigned char*)central)[m] != 0);
        bool bb  = fB ? (((const int*)backbone)[m] != 0) : (((const unsigned char*)backbone)[m] != 0);
        bool base = !bb;
        scond[t] = (nv == 0) || (cen && base) || ((nv == 2) && base);
        sob[t] = obatch[m];
    }
    __syncthreads();
    // 256 threads = 128 channels x 2 obj-halves (halved serial chain)
    const int c = t & 127, half = t >> 7;
    float wnk[NDD];
    #pragma unroll
    for (int k = 0; k < NDD; k++) wnk[k] = Wn[k*HH + c];
    const float bnc = bn[c];
    float acc = 0.f, cntloc = 0.f; int cur_g = -1;
    const int mlo = half*16, mhi = mlo + 16;
    for (int mm = mlo; mm < mhi; mm++) {
        if (!scond[mm]) continue;
        int g = sob[mm];
        float e = bnc;
        #pragma unroll
        for (int k = 0; k < 13; k++) e += sox[mm*13 + k] * wnk[k];
        #pragma unroll
        for (int k = 0; k < 3; k++)  e += sop[mm*3 + k] * wnk[13 + k];
        if (g != cur_g) {
            if (cur_g >= 0) {
                atomicAdd(&g_condsum[cur_g*HH + c], acc);
                if (c == 0) atomicAdd(&g_condcnt[cur_g], cntloc);
            }
            cur_g = g; acc = e; cntloc = 1.f;
        } else { acc += e; cntloc += 1.f; }
    }
    if (cur_g >= 0) {
        atomicAdd(&g_condsum[cur_g*HH + c], acc);
        if (c == 0) atomicAdd(&g_condcnt[cur_g], cntloc);
    }
}

// ============ K2: dinv (block 0) + graph_h (blocks 1..8, self-clean) =========
__global__ void k_dinv_graph(const int* __restrict__ timestep,
                             const float* __restrict__ Wt, const float* __restrict__ bt,
                             const float* __restrict__ Wc, const float* __restrict__ bc) {
    if (blockIdx.x == 0) {
        const int t = threadIdx.x;
        #pragma unroll
        for (int j = 0; j < 4; j++) {
            int i = t + j*1024;
            g_dinv[i] = rsqrtf((float)(g_cnt[i] + 1));
        }
        return;
    }
    __shared__ float te[HH], pe[HH];
    const int g = blockIdx.x - 1, c = threadIdx.x;
    if (c < HH) {
        float tv = (float)timestep[g];
        const float L = 9.210340371976184f;
        if (c < 64) te[c] = cosf(tv * expf(-L * (float)c / 64.f));
        else        te[c] = sinf(tv * expf(-L * (float)(c - 64) / 64.f));
        float cntv = g_condcnt[g];
        pe[c] = g_condsum[g*HH + c] / fmaxf(cntv, 1.0f);
        g_condsum[g*HH + c] = 0.f;
    }
    __syncthreads();
    if (c == 0) g_condcnt[g] = 0.f;
    if (c < HH) {
        float a = bt[c] + bc[c];
        #pragma unroll 8
        for (int k = 0; k < HH; k++)
            a += te[k] * Wt[k*HH + c] + pe[k] * Wc[k*HH + c];
        g_gh[g*HH + c] = a;
    }
}

// ================= K3: gemm1 (32 rows/block, fused node embedding) ===========
#define SMEM1 ((HH*WSP + 32*WSP + 32*NDD + HH + 32) * 4)
__global__ void __launch_bounds__(512, 2)
k_gemm1(const float* __restrict__ W1,
        const float* __restrict__ x, const int* __restrict__ bmap,
        const float* __restrict__ Wn, const float* __restrict__ bn) {
    extern __shared__ float sm[];
    float* Ws  = sm;                        // 128 x 132 (k-major, padded)
    float* As  = sm + HH*WSP;               // 32 x 132
    float* xr  = As + 32*WSP;               // 32 x 16
    float* bns = xr + 32*NDD;               // 128
    int*   gidx = (int*)(bns + HH);         // 32

    const int i0 = blockIdx.x * 32;
    const int t = threadIdx.x;
    const int lane = t & 31, w = t >> 5;    // warp 0..15

    #pragma unroll
    for (int kt = 0; kt < 8; kt++) {
        int k = kt*16 + w;
        float4 v = ((const float4*)(W1 + k*HH))[lane];
        *(float4*)(Ws + k*WSP + lane*4) = v;
    }
    if (t < 128) bns[t] = bn[t];
    if (t < 32) gidx[t] = bmap[i0 + t];
    xr[t] = x[i0*NDD + t];                  // 512 = 32*16
    __syncthreads();

    {
        const int c = t & 127, rg = t >> 7;     // rg 0..3
        float wnk[NDD];
        #pragma unroll
        for (int k = 0; k < NDD; k++) wnk[k] = Wn[k*HH + c];
        #pragma unroll
        for (int r8 = 0; r8 < 8; r8++) {
            int r = rg*8 + r8;
            float a = bns[c] + g_gh[gidx[r]*HH + c];
            #pragma unroll
            for (int k = 0; k < NDD; k++) a += xr[r*NDD + k] * wnk[k];
            As[r*WSP + c] = a;
        }
    }
    __syncthreads();

    const int g = lane >> 2, tig = lane & 3;
    const int rgb = w >> 3, wn = w & 7;
    const int n0 = wn * 16;
    float c0[4] = {0,0,0,0}, c1[4] = {0,0,0,0};
    const float* A0 = As + (rgb*16 + g)*WSP;
    const float* A1 = As + (rgb*16 + 8 + g)*WSP;
    #pragma unroll
    for (int kt = 0; kt < 16; kt++) {
        int k0 = kt*8;
        float av0 = A0[k0+tig],   av1 = A1[k0+tig];
        float av2 = A0[k0+tig+4], av3 = A1[k0+tig+4];
        unsigned ah0 = hi_of(av0), ah1 = hi_of(av1), ah2 = hi_of(av2), ah3 = hi_of(av3);
        unsigned al0 = lo_of(av0,ah0), al1 = lo_of(av1,ah1);
        unsigned al2 = lo_of(av2,ah2), al3 = lo_of(av3,ah3);
        const float* B0 = Ws + (k0+tig)*WSP;
        const float* B1 = Ws + (k0+tig+4)*WSP;
        float bv0 = B0[n0+g], bv1 = B1[n0+g], bv2 = B0[n0+8+g], bv3 = B1[n0+8+g];
        unsigned bh0 = hi_of(bv0), bh1 = hi_of(bv1), bh2 = hi_of(bv2), bh3 = hi_of(bv3);
        unsigned bl0 = lo_of(bv0,bh0), bl1 = lo_of(bv1,bh1);
        unsigned bl2 = lo_of(bv2,bh2), bl3 = lo_of(bv3,bh3);
        mma_tf32(c0, ah0,ah1,ah2,ah3, bh0,bh1);
        mma_tf32(c0, ah0,ah1,ah2,ah3, bl0,bl1);
        mma_tf32(c0, al0,al1,al2,al3, bh0,bh1);
        mma_tf32(c1, ah0,ah1,ah2,ah3, bh2,bh3);
        mma_tf32(c1, ah0,ah1,ah2,ah3, bl2,bl3);
        mma_tf32(c1, al0,al1,al2,al3, bh2,bh3);
    }
    const int r0 = i0 + rgb*16 + g, r1 = r0 + 8;
    const float d0 = g_dinv[r0], d1 = g_dinv[r1];
    *(float2*)&g_buf[0][r0*HH + n0 + 2*tig]     = make_float2(d0*c0[0], d0*c0[1]);
    *(float2*)&g_buf[0][r0*HH + n0 + 8 + 2*tig] = make_float2(d0*c1[0], d0*c1[1]);
    *(float2*)&g_buf[0][r1*HH + n0 + 2*tig]     = make_float2(d1*c0[2], d1*c0[3]);
    *(float2*)&g_buf[0][r1*HH + n0 + 8 + 2*tig] = make_float2(d1*c1[2], d1*c1[3]);
}

// ================= K4: agg1 + gemm2 fused (16 nodes/block, 2/SM) =============
#define SMEM2 ((HH*WSP + 16*WSP) * 4)
__global__ void __launch_bounds__(512, 2)
k_agg_gemm2(const float* __restrict__ b1, const float* __restrict__ W2) {
    extern __shared__ float sm[];
    float* Ws = sm;                 // 128 x 132
    float* As = sm + HH*WSP;        // 16 x 132
    const int t = threadIdx.x;
    const int lane = t & 31, w = t >> 5;   // warp 0..15

    #pragma unroll
    for (int kt = 0; kt < 8; kt++) {
        int k = kt*16 + w;
        float4 v = ((const float4*)(W2 + k*HH))[lane];
        *(float4*)(Ws + k*WSP + lane*4) = v;
    }

    const int i = blockIdx.x*16 + w;
    const float4* __restrict__ xw = (const float4*)g_buf[0];
    float4 acc = xw[i*32 + lane];
    const int* csr = g_csr2 + (i << 7);
    const int deg = g_cnt[i];
    int e = 0;
    for (; e + 8 <= deg; e += 8) {
        int a0 = csr[e],   a1 = csr[e+1], a2 = csr[e+2], a3 = csr[e+3];
        int a4 = csr[e+4], a5 = csr[e+5], a6 = csr[e+6], a7 = csr[e+7];
        float4 v0 = xw[a0*32 + lane], v1 = xw[a1*32 + lane];
        float4 v2 = xw[a2*32 + lane], v3 = xw[a3*32 + lane];
        float4 v4 = xw[a4*32 + lane], v5 = xw[a5*32 + lane];
        float4 v6 = xw[a6*32 + lane], v7 = xw[a7*32 + lane];
        acc.x += ((v0.x+v1.x)+(v2.x+v3.x)) + ((v4.x+v5.x)+(v6.x+v7.x));
        acc.y += ((v0.y+v1.y)+(v2.y+v3.y)) + ((v4.y+v5.y)+(v6.y+v7.y));
        acc.z += ((v0.z+v1.z)+(v2.z+v3.z)) + ((v4.z+v5.z)+(v6.z+v7.z));
        acc.w += ((v0.w+v1.w)+(v2.w+v3.w)) + ((v4.w+v5.w)+(v6.w+v7.w));
    }
    for (; e + 4 <= deg; e += 4) {
        int a0 = csr[e], a1 = csr[e+1], a2 = csr[e+2], a3 = csr[e+3];
        float4 v0 = xw[a0*32 + lane], v1 = xw[a1*32 + lane];
        float4 v2 = xw[a2*32 + lane], v3 = xw[a3*32 + lane];
        acc.x += (v0.x+v1.x)+(v2.x+v3.x);
        acc.y += (v0.y+v1.y)+(v2.y+v3.y);
        acc.z += (v0.z+v1.z)+(v2.z+v3.z);
        acc.w += (v0.w+v1.w)+(v2.w+v3.w);
    }
    for (; e < deg; e++) {
        float4 v = xw[csr[e]*32 + lane];
        acc.x += v.x; acc.y += v.y; acc.z += v.z; acc.w += v.w;
    }
    {
        const float di = g_dinv[i];
        const float4 b4 = ((const float4*)b1)[lane];
        float4 h;
        h.x = fmaxf(di*acc.x + b4.x, 0.f);
        h.y = fmaxf(di*acc.y + b4.y, 0.f);
        h.z = fmaxf(di*acc.z + b4.z, 0.f);
        h.w = fmaxf(di*acc.w + b4.w, 0.f);
        ((float4*)(As + w*WSP))[lane] = h;
    }
    __syncthreads();

    const int g = lane >> 2, tig = lane & 3;
    const int n0 = w * 8;
    float c0[4] = {0,0,0,0};
    const float* A0 = As + g*WSP;
    const float* A1 = As + (8 + g)*WSP;
    #pragma unroll
    for (int kt = 0; kt < 16; kt++) {
        int k0 = kt*8;
        float av0 = A0[k0+tig],   av1 = A1[k0+tig];
        float av2 = A0[k0+tig+4], av3 = A1[k0+tig+4];
        unsigned ah0 = hi_of(av0), ah1 = hi_of(av1), ah2 = hi_of(av2), ah3 = hi_of(av3);
        unsigned al0 = lo_of(av0,ah0), al1 = lo_of(av1,ah1);
        unsigned al2 = lo_of(av2,ah2), al3 = lo_of(av3,ah3);
        const float* B0 = Ws + (k0+tig)*WSP;
        const float* B1 = Ws + (k0+tig+4)*WSP;
        float bv0 = B0[n0+g], bv1 = B1[n0+g];
        unsigned bh0 = hi_of(bv0), bh1 = hi_of(bv1);
        unsigned bl0 = lo_of(bv0,bh0), bl1 = lo_of(bv1,bh1);
        mma_tf32(c0, ah0,ah1,ah2,ah3, bh0,bh1);
        mma_tf32(c0, ah0,ah1,ah2,ah3, bl0,bl1);
        mma_tf32(c0, al0,al1,al2,al3, bh0,bh1);
    }
    const int i0 = blockIdx.x*16;
    const int r0 = i0 + g, r1 = r0 + 8;
    const float d0 = g_dinv[r0], d1 = g_dinv[r1];
    *(float2*)&g_buf[1][r0*HH + n0 + 2*tig] = make_float2(d0*c0[0], d0*c0[1]);
    *(float2*)&g_buf[1][r1*HH + n0 + 2*tig] = make_float2(d1*c0[2], d1*c0[3]);
}

// ============ K5: agg2 + head fused (warp-per-node; zeroes g_cnt) ============
__global__ void k_agg_head(const float* __restrict__ bias,
                           const float* __restrict__ Wo, const float* __restrict__ bo,
                           const float* __restrict__ we, float* __restrict__ out_nodes) {
    const int i = (blockIdx.x * blockDim.x + threadIdx.x) >> 5;
    if (i >= NN) return;
    const int lane = threadIdx.x & 31;
    const float4* __restrict__ xw = (const float4*)g_buf[1];
    float4 acc = xw[i*32 + lane];
    const int* csr = g_csr2 + (i << 7);
    const int deg = g_cnt[i];
    if (lane == 0) g_cnt[i] = 0;            // self-clean for next replay
    int e = 0;
    for (; e + 8 <= deg; e += 8) {
        int a0 = csr[e],   a1 = csr[e+1], a2 = csr[e+2], a3 = csr[e+3];
        int a4 = csr[e+4], a5 = csr[e+5], a6 = csr[e+6], a7 = csr[e+7];
        float4 v0 = xw[a0*32 + lane], v1 = xw[a1*32 + lane];
        float4 v2 = xw[a2*32 + lane], v3 = xw[a3*32 + lane];
        float4 v4 = xw[a4*32 + lane], v5 = xw[a5*32 + lane];
        float4 v6 = xw[a6*32 + lane], v7 = xw[a7*32 + lane];
        acc.x += ((v0.x+v1.x)+(v2.x+v3.x)) + ((v4.x+v5.x)+(v6.x+v7.x));
        acc.y += ((v0.y+v1.y)+(v2.y+v3.y)) + ((v4.y+v5.y)+(v6.y+v7.y));
        acc.z += ((v0.z+v1.z)+(v2.z+v3.z)) + ((v4.z+v5.z)+(v6.z+v7.z));
        acc.w += ((v0.w+v1.w)+(v2.w+v3.w)) + ((v4.w+v5.w)+(v6.w+v7.w));
    }
    for (; e + 4 <= deg; e += 4) {
        int a0 = csr[e], a1 = csr[e+1], a2 = csr[e+2], a3 = csr[e+3];
        float4 v0 = xw[a0*32 + lane], v1 = xw[a1*32 + lane];
        float4 v2 = xw[a2*32 + lane], v3 = xw[a3*32 + lane];
        acc.x += (v0.x+v1.x)+(v2.x+v3.x);
        acc.y += (v0.y+v1.y)+(v2.y+v3.y);
        acc.z += (v0.z+v1.z)+(v2.z+v3.z);
        acc.w += (v0.w+v1.w)+(v2.w+v3.w);
    }
    for (; e < deg; e++) {
        float4 v = xw[csr[e]*32 + lane];
        acc.x += v.x; acc.y += v.y; acc.z += v.z; acc.w += v.w;
    }
    const float di = g_dinv[i];
    const float4 b4 = ((const float4*)bias)[lane];
    float4 h;
    h.x = fmaxf(di*acc.x + b4.x, 0.f);
    h.y = fmaxf(di*acc.y + b4.y, 0.f);
    h.z = fmaxf(di*acc.z + b4.z, 0.f);
    h.w = fmaxf(di*acc.w + b4.w, 0.f);

    const float4 wl4 = ((const float4*)we)[lane];
    const float4 wr4 = ((const float4*)we)[32 + lane];
    float pl = h.x*wl4.x + h.y*wl4.y + h.z*wl4.z + h.w*wl4.w;
    float pr = h.x*wr4.x + h.y*wr4.y + h.z*wr4.z + h.w*wr4.w;

    float p[NDD];
    #pragma unroll
    for (int c = 0; c < NDD; c++) p[c] = 0.f;
    const float4* Wo4 = (const float4*)Wo;
    float hv[4] = {h.x, h.y, h.z, h.w};
    #pragma unroll
    for (int j = 0; j < 4; j++) {
        int k = lane*4 + j;
        #pragma unroll
        for (int c4 = 0; c4 < 4; c4++) {
            float4 wv = Wo4[k*4 + c4];
            p[c4*4+0] += hv[j]*wv.x; p[c4*4+1] += hv[j]*wv.y;
            p[c4*4+2] += hv[j]*wv.z; p[c4*4+3] += hv[j]*wv.w;
        }
    }
    #pragma unroll
    for (int off = 16; off > 0; off >>= 1) {
        pl += __shfl_down_sync(0xffffffffu, pl, off);
        pr += __shfl_down_sync(0xffffffffu, pr, off);
        #pragma unroll
        for (int c = 0; c < NDD; c++)
            p[c] += __shfl_down_sync(0xffffffffu, p[c], off);
    }
    if (lane == 0) {
        g_sl[i] = pl;
        g_sr[i] = pr;
        float4* on4 = (float4*)(out_nodes + i*NDD);
        const float4* bo4 = (const float4*)bo;
        #pragma unroll
        for (int c4 = 0; c4 < 4; c4++) {
            float4 b = bo4[c4];
            float4 v;
            v.x = p[c4*4+0] + b.x; v.y = p[c4*4+1] + b.y;
            v.z = p[c4*4+2] + b.z; v.w = p[c4*4+3] + b.w;
            on4[c4] = v;
        }
    }
}

// ================= K6: edges (row-pair balanced, float4 stores) ===============
__global__ void k_edges(const float* __restrict__ bedge, float* __restrict__ out_edges) {
    const float be = bedge[0];
    const int bi = blockIdx.x;
    const int t = threadIdx.x;
    #pragma unroll
    for (int half = 0; half < 2; half++) {
        const int i = (half == 0) ? bi : (NN - 2 - bi);
        if (half == 1 && i <= bi) break;
        const int cnt = NN - 1 - i;
        const long long off = (long long)i * (2LL*NN - i - 1) / 2;
        const float sl = g_sl[i] + be;
        float* o = out_edges + off;
        const float* sr = g_sr + i + 1;
        const int pre0 = (int)((4 - (off & 3)) & 3);
        const int pre = pre0 < cnt ? pre0 : cnt;
        if (t < pre) o[t] = sl + sr[t];
        const int nv = (cnt - pre) >> 2;
        float4* o4 = (float4*)(o + pre);
        for (int v = t; v < nv; v += 256) {
            int j = pre + v*4;
            float4 r;
            r.x = sl + sr[j];   r.y = sl + sr[j+1];
            r.z = sl + sr[j+2]; r.w = sl + sr[j+3];
            o4[v] = r;
        }
        const int tail0 = pre + nv*4;
        const int rem = cnt - tail0;
        if (t < rem) o[tail0 + t] = sl + sr[tail0 + t];
    }
}

// ================= launch =================
extern "C" void kernel_launch(void* const* d_in, const int* in_sizes, int n_in,
                              void* d_out, int out_size) {
    const float* x        = (const float*)d_in[0];
    const int*   eidx     = (const int*)d_in[1];
    const int*   timestep = (const int*)d_in[2];
    const int*   bmap     = (const int*)d_in[3];
    const int*   nuc      = (const int*)d_in[4];
    const void*  central  = d_in[5];
    const void*  backbone = d_in[6];
    const float* obj_x    = (const float*)d_in[7];
    const float* obj_pos  = (const float*)d_in[8];
    const int*   obatch   = (const int*)d_in[9];
    const float* Wn = (const float*)d_in[10]; const float* bn = (const float*)d_in[11];
    const float* Wc = (const float*)d_in[12]; const float* bc = (const float*)d_in[13];
    const float* Wt = (const float*)d_in[14]; const float* bt = (const float*)d_in[15];
    const float* W1 = (const float*)d_in[16]; const float* b1 = (const float*)d_in[17];
    const float* W2 = (const float*)d_in[18]; const float* b2 = (const float*)d_in[19];
    const float* Wo = (const float*)d_in[20]; const float* bo = (const float*)d_in[21];
    const float* we = (const float*)d_in[22]; const float* be = (const float*)d_in[23];

    float* out = (float*)d_out;
    float* out_nodes = out;
    float* out_edges = out + NN*NDD;

    const int* esrc = eidx;
    const int* edst = eidx + EE;

    cudaFuncSetAttribute(k_gemm1,     cudaFuncAttributeMaxDynamicSharedMemorySize, SMEM1);
    cudaFuncSetAttribute(k_agg_gemm2, cudaFuncAttributeMaxDynamicSharedMemorySize, SMEM2);

    k_hist_cond<<<384, 256>>>(esrc, edst, obj_x, obj_pos, nuc, central, backbone, obatch, Wn, bn);
    k_dinv_graph<<<9, 1024>>>(timestep, Wt, bt, Wc, bc);
    k_gemm1<<<NN/32, 512, SMEM1>>>(W1, x, bmap, Wn, bn);
    k_agg_gemm2<<<NN/16, 512, SMEM2>>>(b1, W2);
    k_agg_head<<<NN/8, 256>>>(b2, Wo, bo, we, out_nodes);
    k_edges<<<NN/2, 256>>>(be, out_edges);
}